// round 1
// baseline (speedup 1.0000x reference)
#include <cuda_runtime.h>

// Problem constants
#define T_STEPS 168
#define IN_DIM  16
#define NH1     64
#define NH2     32
#define NG1     256   // 4*H1
#define NG2     128   // 4*H2
#define BATCH   4096

// Tiling
#define NB   14       // batch elements per CTA
#define BLK  256      // threads per CTA
#define GRID ((BATCH + NB - 1) / NB)   // 293

// Shared layouts (float counts). Strides chosen == 0 (mod 4) for float4
// alignment and == 4 (mod 8) for conflict-free LDS.128 across lanes.
#define W1_STRIDE  84    // 16 (x) + 64 (h1) + 4 pad
#define W2_STRIDE  100   // 64 (h1) + 32 (h2) + 4 pad
#define IN1_STRIDE 80    // [0:16]=x_t  [16:80]=h1
#define IN2_STRIDE 96    // [0:64]=h1_t [64:96]=h2

#define OFF_W1   0
#define OFF_W2   (OFF_W1  + NG1 * W1_STRIDE)   // 21504
#define OFF_B1   (OFF_W2  + NG2 * W2_STRIDE)   // +12800
#define OFF_B2   (OFF_B1  + NG1)
#define OFF_WFC  (OFF_B2  + NG2)
#define OFF_IN1  (OFF_WFC + 32)
#define OFF_IN2  (OFF_IN1 + NB * IN1_STRIDE)
#define OFF_G1   (OFF_IN2 + NB * IN2_STRIDE)
#define OFF_G2   (OFF_G1  + NB * NG1)
#define SMEM_FLOATS (OFF_G2 + NB * NG2)        // 42560 floats = 170240 B

__device__ __forceinline__ float sigm_(float v) {
    v = fminf(fmaxf(v, -30.f), 30.f);
    return __fdividef(1.f, 1.f + __expf(-v));
}
__device__ __forceinline__ float tanh_(float v) {
    v = fminf(fmaxf(v, -15.f), 15.f);
    float e = __expf(2.f * v);
    return __fdividef(e - 1.f, e + 1.f);
}

extern __shared__ float smem[];

__global__ __launch_bounds__(BLK, 1)
void lstm2_fused_kernel(const float* __restrict__ x,
                        const float* __restrict__ Wih1, const float* __restrict__ Whh1,
                        const float* __restrict__ bih1, const float* __restrict__ bhh1,
                        const float* __restrict__ Wih2, const float* __restrict__ Whh2,
                        const float* __restrict__ bih2, const float* __restrict__ bhh2,
                        const float* __restrict__ Wfc,  const float* __restrict__ bfc,
                        float* __restrict__ out)
{
    const int tid = threadIdx.x;
    const int b0  = blockIdx.x * NB;

    float* sW1  = smem + OFF_W1;
    float* sW2  = smem + OFF_W2;
    float* sB1  = smem + OFF_B1;
    float* sB2  = smem + OFF_B2;
    float* sWfc = smem + OFF_WFC;
    float* sIn1 = smem + OFF_IN1;
    float* sIn2 = smem + OFF_IN2;
    float* sG1  = smem + OFF_G1;
    float* sG2  = smem + OFF_G2;

    // ---- load weights into shared (combined [x;h] rows, padded strides) ----
    for (int i = tid; i < NG1 * W1_STRIDE; i += BLK) {
        int g = i / W1_STRIDE, k = i % W1_STRIDE;
        float v = 0.f;
        if (k < IN_DIM)               v = Wih1[g * IN_DIM + k];
        else if (k < IN_DIM + NH1)    v = Whh1[g * NH1 + (k - IN_DIM)];
        sW1[i] = v;
    }
    for (int i = tid; i < NG2 * W2_STRIDE; i += BLK) {
        int g = i / W2_STRIDE, k = i % W2_STRIDE;
        float v = 0.f;
        if (k < NH1)                  v = Wih2[g * NH1 + k];
        else if (k < NH1 + NH2)       v = Whh2[g * NH2 + (k - NH1)];
        sW2[i] = v;
    }
    if (tid < NG1) sB1[tid] = bih1[tid] + bhh1[tid];
    if (tid < NG2) sB2[tid] = bih2[tid] + bhh2[tid];
    if (tid < NH2) sWfc[tid] = Wfc[tid];
    for (int i = tid; i < NB * IN1_STRIDE; i += BLK) sIn1[i] = 0.f;
    for (int i = tid; i < NB * IN2_STRIDE; i += BLK) sIn2[i] = 0.f;

    // cell states in registers
    float c1[NB], c2[NB];
#pragma unroll
    for (int b = 0; b < NB; b++) { c1[b] = 0.f; c2[b] = 0.f; }

    // x prefetch for t=0 (224 threads: one (b,k) element each)
    const int  xb   = tid >> 4;
    const int  xk   = tid & 15;
    const bool xact = (tid < NB * IN_DIM);
    const bool xval = xact && (b0 + xb) < BATCH;
    const long xbase = ((long)(b0 + xb) * T_STEPS) * IN_DIM + xk;
    float xreg = 0.f;
    if (xval) xreg = x[xbase];

    __syncthreads();

    const int g = tid;

    for (int t = 0; t < T_STEPS; t++) {
        // ---- phase 1: publish x_t, prefetch x_{t+1} ----
        if (xact) sIn1[xb * IN1_STRIDE + xk] = xreg;
        __syncthreads();
        if (xval && (t + 1) < T_STEPS) xreg = x[xbase + (long)(t + 1) * IN_DIM];

        // ---- phase 2: layer-1 gates (all 256 threads, thread == gate) ----
        {
            float acc[NB];
            const float bb = sB1[g];
#pragma unroll
            for (int b = 0; b < NB; b++) acc[b] = bb;
#pragma unroll 4
            for (int k4 = 0; k4 < IN1_STRIDE / 4; k4++) {
                const float4 w = *(const float4*)&sW1[g * W1_STRIDE + k4 * 4];
#pragma unroll
                for (int b = 0; b < NB; b++) {
                    const float4 h = *(const float4*)&sIn1[b * IN1_STRIDE + k4 * 4];
                    acc[b] = fmaf(w.x, h.x, acc[b]);
                    acc[b] = fmaf(w.y, h.y, acc[b]);
                    acc[b] = fmaf(w.z, h.z, acc[b]);
                    acc[b] = fmaf(w.w, h.w, acc[b]);
                }
            }
            const int grp = g >> 6;   // 0:i 1:f 2:g 3:o
#pragma unroll
            for (int b = 0; b < NB; b++) {
                const float v = (grp == 2) ? tanh_(acc[b]) : sigm_(acc[b]);
                sG1[b * NG1 + g] = v;
            }
        }
        __syncthreads();

        // ---- phase 3: layer-1 cell update (threads 0..63, thread == unit) ----
        if (tid < NH1) {
            const int u = tid;
#pragma unroll
            for (int b = 0; b < NB; b++) {
                const float i_ = sG1[b * NG1 + u];
                const float f_ = sG1[b * NG1 + NH1 + u];
                const float g_ = sG1[b * NG1 + 2 * NH1 + u];
                const float o_ = sG1[b * NG1 + 3 * NH1 + u];
                const float c  = fmaf(f_, c1[b], i_ * g_);
                c1[b] = c;
                const float h = o_ * tanh_(c);
                sIn1[b * IN1_STRIDE + IN_DIM + u] = h;
                sIn2[b * IN2_STRIDE + u]          = h;
            }
        }
        __syncthreads();

        // ---- phase 4: layer-2 gates (threads 0..127, thread == gate) ----
        if (tid < NG2) {
            float acc[NB];
            const float bb = sB2[g];
#pragma unroll
            for (int b = 0; b < NB; b++) acc[b] = bb;
#pragma unroll 4
            for (int k4 = 0; k4 < IN2_STRIDE / 4; k4++) {
                const float4 w = *(const float4*)&sW2[g * W2_STRIDE + k4 * 4];
#pragma unroll
                for (int b = 0; b < NB; b++) {
                    const float4 h = *(const float4*)&sIn2[b * IN2_STRIDE + k4 * 4];
                    acc[b] = fmaf(w.x, h.x, acc[b]);
                    acc[b] = fmaf(w.y, h.y, acc[b]);
                    acc[b] = fmaf(w.z, h.z, acc[b]);
                    acc[b] = fmaf(w.w, h.w, acc[b]);
                }
            }
            const int grp = g >> 5;   // 0:i 1:f 2:g 3:o
#pragma unroll
            for (int b = 0; b < NB; b++) {
                const float v = (grp == 2) ? tanh_(acc[b]) : sigm_(acc[b]);
                sG2[b * NG2 + g] = v;
            }
        }
        __syncthreads();

        // ---- phase 5: layer-2 cell update (threads 0..31) ----
        if (tid < NH2) {
            const int u = tid;
#pragma unroll
            for (int b = 0; b < NB; b++) {
                const float i_ = sG2[b * NG2 + u];
                const float f_ = sG2[b * NG2 + NH2 + u];
                const float g_ = sG2[b * NG2 + 2 * NH2 + u];
                const float o_ = sG2[b * NG2 + 3 * NH2 + u];
                const float c  = fmaf(f_, c2[b], i_ * g_);
                c2[b] = c;
                sIn2[b * IN2_STRIDE + NH1 + u] = o_ * tanh_(c);
            }
        }
        __syncthreads();
    }

    // ---- final FC: out[b] = h2_last . Wfc + bfc ----
    if (tid < NB) {
        const int bg = b0 + tid;
        if (bg < BATCH) {
            float s = bfc[0];
#pragma unroll
            for (int u = 0; u < NH2; u++)
                s = fmaf(sIn2[tid * IN2_STRIDE + NH1 + u], sWfc[u], s);
            out[bg] = s;
        }
    }
}

extern "C" void kernel_launch(void* const* d_in, const int* in_sizes, int n_in,
                              void* d_out, int out_size)
{
    const float* x    = (const float*)d_in[0];
    const float* Wih1 = (const float*)d_in[1];
    const float* Whh1 = (const float*)d_in[2];
    const float* bih1 = (const float*)d_in[3];
    const float* bhh1 = (const float*)d_in[4];
    const float* Wih2 = (const float*)d_in[5];
    const float* Whh2 = (const float*)d_in[6];
    const float* bih2 = (const float*)d_in[7];
    const float* bhh2 = (const float*)d_in[8];
    const float* Wfc  = (const float*)d_in[9];
    const float* bfc  = (const float*)d_in[10];
    float* out = (float*)d_out;

    const size_t smem_bytes = SMEM_FLOATS * sizeof(float);  // ~170 KB
    cudaFuncSetAttribute(lstm2_fused_kernel,
                         cudaFuncAttributeMaxDynamicSharedMemorySize,
                         (int)smem_bytes);

    lstm2_fused_kernel<<<GRID, BLK, smem_bytes>>>(
        x, Wih1, Whh1, bih1, bhh1, Wih2, Whh2, bih2, bhh2, Wfc, bfc, out);
}

// round 2
// speedup vs baseline: 1.1206x; 1.1206x over previous
#include <cuda_runtime.h>

// Problem constants
#define T_STEPS 168
#define IN_DIM  16
#define NH1     64
#define NH2     32
#define NG1     256   // 4*H1
#define NG2     128   // 4*H2
#define BATCH   4096

// Tiling: one wave — 147 CTAs on 148 SMs
#define NB   28
#define NBH  14              // batches per half (phase 4 split)
#define BLK  256
#define GRID ((BATCH + NB - 1) / NB)   // 147

// Strides (floats): ≡ 0 mod 4 (float4 align), ≡ 4 mod 8 (conflict-free LDS.128)
#define W1_STRIDE  84    // 16 (x) + 64 (h1) + 4 pad
#define W2_STRIDE  100   // 64 (h1) + 32 (h2) + 4 pad
#define IN1_STRIDE 84
#define IN2_STRIDE 100

#define OFF_W1   0
#define OFF_W2   (OFF_W1  + NG1 * W1_STRIDE)    // 21504
#define OFF_B1   (OFF_W2  + NG2 * W2_STRIDE)    // 34304
#define OFF_B2   (OFF_B1  + NG1)                // 34560
#define OFF_WFC  (OFF_B2  + NG2)                // 34688
#define OFF_IN1  (OFF_WFC + 32)                 // 34720
#define OFF_IN2  (OFF_IN1 + NB * IN1_STRIDE)    // 37072
#define OFF_G1   (OFF_IN2 + NB * IN2_STRIDE)    // 39872
#define OFF_G2   (OFF_G1  + NB * NG1)           // 47040
#define OFF_C1   (OFF_G2  + NB * NG2)           // 50624
#define OFF_C2   (OFF_C1  + NB * NH1)           // 52416
#define SMEM_FLOATS (OFF_C2 + NB * NH2)         // 53312 floats = 213248 B

typedef unsigned long long u64;

__device__ __forceinline__ void fma2(u64& d, u64 a, u64 b) {
    asm("fma.rn.f32x2 %0, %1, %2, %0;" : "+l"(d) : "l"(a), "l"(b));
}
__device__ __forceinline__ float pairsum(u64 v) {
    float lo, hi;
    asm("mov.b64 {%0, %1}, %2;" : "=f"(lo), "=f"(hi) : "l"(v));
    return lo + hi;
}

__device__ __forceinline__ float sigm_(float v) {
    v = fminf(fmaxf(v, -30.f), 30.f);
    return __fdividef(1.f, 1.f + __expf(-v));
}
__device__ __forceinline__ float tanh_(float v) {
    v = fminf(fmaxf(v, -15.f), 15.f);
    float e = __expf(2.f * v);
    return __fdividef(e - 1.f, e + 1.f);
}

extern __shared__ float smem[];

__global__ __launch_bounds__(BLK, 1)
void lstm2_fused_kernel(const float* __restrict__ x,
                        const float* __restrict__ Wih1, const float* __restrict__ Whh1,
                        const float* __restrict__ bih1, const float* __restrict__ bhh1,
                        const float* __restrict__ Wih2, const float* __restrict__ Whh2,
                        const float* __restrict__ bih2, const float* __restrict__ bhh2,
                        const float* __restrict__ Wfc,  const float* __restrict__ bfc,
                        float* __restrict__ out)
{
    const int tid = threadIdx.x;
    const int b0  = blockIdx.x * NB;

    float* sW1  = smem + OFF_W1;
    float* sW2  = smem + OFF_W2;
    float* sB1  = smem + OFF_B1;
    float* sB2  = smem + OFF_B2;
    float* sWfc = smem + OFF_WFC;
    float* sIn1 = smem + OFF_IN1;
    float* sIn2 = smem + OFF_IN2;
    float* sG1  = smem + OFF_G1;
    float* sG2  = smem + OFF_G2;
    float* sC1  = smem + OFF_C1;
    float* sC2  = smem + OFF_C2;

    // ---- weights into shared (combined [x;h] rows, padded strides) ----
    for (int i = tid; i < NG1 * W1_STRIDE; i += BLK) {
        int g = i / W1_STRIDE, k = i % W1_STRIDE;
        float v = 0.f;
        if (k < IN_DIM)            v = Wih1[g * IN_DIM + k];
        else if (k < IN_DIM + NH1) v = Whh1[g * NH1 + (k - IN_DIM)];
        sW1[i] = v;
    }
    for (int i = tid; i < NG2 * W2_STRIDE; i += BLK) {
        int g = i / W2_STRIDE, k = i % W2_STRIDE;
        float v = 0.f;
        if (k < NH1)            v = Wih2[g * NH1 + k];
        else if (k < NH1 + NH2) v = Whh2[g * NH2 + (k - NH1)];
        sW2[i] = v;
    }
    if (tid < NG1) sB1[tid] = bih1[tid] + bhh1[tid];
    if (tid < NG2) sB2[tid] = bih2[tid] + bhh2[tid];
    if (tid < NH2) sWfc[tid] = Wfc[tid];
    for (int i = tid; i < NB * IN1_STRIDE; i += BLK) sIn1[i] = 0.f;
    for (int i = tid; i < NB * IN2_STRIDE; i += BLK) sIn2[i] = 0.f;
    for (int i = tid; i < NB * NH1; i += BLK) sC1[i] = 0.f;
    for (int i = tid; i < NB * NH2; i += BLK) sC2[i] = 0.f;

    // ---- x prefetch: 112 threads each own one float4 (b, k4) ----
    const bool xact = (tid < NB * (IN_DIM / 4));          // 112
    const int  xb   = tid >> 2;
    const int  xk4  = tid & 3;
    const bool xval = xact && (b0 + xb) < BATCH;
    const float* xptr = x + ((long)(b0 + xb) * T_STEPS) * IN_DIM + xk4 * 4;
    float4 xreg = make_float4(0.f, 0.f, 0.f, 0.f);
    if (xval) xreg = *(const float4*)xptr;

    __syncthreads();

    const int g1  = tid;           // layer-1 gate
    const int g2  = tid & 127;     // layer-2 gate
    const int bh  = tid >> 7;      // batch half for phase 4
    const int u3  = tid & 63;      // layer-1 unit, phase 3
    const int bq3 = tid >> 6;      // 4 groups x 7 batches
    const int u5  = tid & 31;      // layer-2 unit, phase 5
    const int bq5 = tid >> 5;      // 8 groups x 4 batches (group 7 idle)

    const float* w1row = sW1 + g1 * W1_STRIDE;
    const float* w2row = sW2 + g2 * W2_STRIDE;
    const float  bb1   = sB1[g1];
    const float  bb2   = sB2[g2];
    const int    grp1  = g1 >> 6;
    const int    grp2  = g2 >> 5;

    for (int t = 0; t < T_STEPS; t++) {
        // ---- phase 1: publish x_t ----
        if (xact) *(float4*)&sIn1[xb * IN1_STRIDE + xk4 * 4] = xreg;
        __syncthreads();                              // A
        if (xval && (t + 1) < T_STEPS)
            xreg = *(const float4*)(xptr + (long)(t + 1) * IN_DIM);

        // ---- phase 2: layer-1 gates, all 256 threads, k packed as f32x2 ----
        {
            u64 acc[NB];
#pragma unroll
            for (int b = 0; b < NB; b++) acc[b] = 0ull;
#pragma unroll 4
            for (int k4 = 0; k4 < (IN_DIM + NH1) / 4; k4++) {      // 20
                const ulonglong2 w = *(const ulonglong2*)(w1row + k4 * 4);
#pragma unroll
                for (int b = 0; b < NB; b++) {
                    const ulonglong2 h = *(const ulonglong2*)(sIn1 + b * IN1_STRIDE + k4 * 4);
                    fma2(acc[b], w.x, h.x);
                    fma2(acc[b], w.y, h.y);
                }
            }
#pragma unroll
            for (int b = 0; b < NB; b++) {
                const float v = pairsum(acc[b]) + bb1;
                sG1[b * NG1 + g1] = (grp1 == 2) ? tanh_(v) : sigm_(v);
            }
        }
        __syncthreads();                              // B

        // ---- phase 3: layer-1 cell/h update, all 256 threads ----
        {
#pragma unroll
            for (int j = 0; j < 7; j++) {
                const int b = bq3 * 7 + j;
                const float i_ = sG1[b * NG1 + u3];
                const float f_ = sG1[b * NG1 + NH1 + u3];
                const float g_ = sG1[b * NG1 + 2 * NH1 + u3];
                const float o_ = sG1[b * NG1 + 3 * NH1 + u3];
                const float c  = fmaf(f_, sC1[b * NH1 + u3], i_ * g_);
                sC1[b * NH1 + u3] = c;
                const float h = o_ * tanh_(c);
                sIn1[b * IN1_STRIDE + IN_DIM + u3] = h;
                sIn2[b * IN2_STRIDE + u3]          = h;
            }
        }
        __syncthreads();                              // C

        // ---- phase 4: layer-2 gates, 256 threads (batch-split halves) ----
        {
            u64 acc[NBH];
#pragma unroll
            for (int b = 0; b < NBH; b++) acc[b] = 0ull;
            const float* in2h = sIn2 + (bh * NBH) * IN2_STRIDE;
#pragma unroll 4
            for (int k4 = 0; k4 < (NH1 + NH2) / 4; k4++) {         // 24
                const ulonglong2 w = *(const ulonglong2*)(w2row + k4 * 4);
#pragma unroll
                for (int b = 0; b < NBH; b++) {
                    const ulonglong2 h = *(const ulonglong2*)(in2h + b * IN2_STRIDE + k4 * 4);
                    fma2(acc[b], w.x, h.x);
                    fma2(acc[b], w.y, h.y);
                }
            }
#pragma unroll
            for (int b = 0; b < NBH; b++) {
                const float v = pairsum(acc[b]) + bb2;
                sG2[(bh * NBH + b) * NG2 + g2] = (grp2 == 2) ? tanh_(v) : sigm_(v);
            }
        }
        __syncthreads();                              // D

        // ---- phase 5: layer-2 cell/h update (224 threads) ----
        if (bq5 < 7) {
#pragma unroll
            for (int j = 0; j < 4; j++) {
                const int b = bq5 * 4 + j;
                const float i_ = sG2[b * NG2 + u5];
                const float f_ = sG2[b * NG2 + NH2 + u5];
                const float g_ = sG2[b * NG2 + 2 * NH2 + u5];
                const float o_ = sG2[b * NG2 + 3 * NH2 + u5];
                const float c  = fmaf(f_, sC2[b * NH2 + u5], i_ * g_);
                sC2[b * NH2 + u5] = c;
                sIn2[b * IN2_STRIDE + NH1 + u5] = o_ * tanh_(c);
            }
        }
        // no sync: next reader of sIn2/sC2 is phase 4 / phase 5 of t+1,
        // separated by barriers A,B,C of the next iteration.
    }

    __syncthreads();

    // ---- final FC: out[b] = h2_last . Wfc + bfc ----
    if (tid < NB) {
        const int bg = b0 + tid;
        if (bg < BATCH) {
            float s = bfc[0];
#pragma unroll
            for (int u = 0; u < NH2; u++)
                s = fmaf(sIn2[tid * IN2_STRIDE + NH1 + u], sWfc[u], s);
            out[bg] = s;
        }
    }
}

extern "C" void kernel_launch(void* const* d_in, const int* in_sizes, int n_in,
                              void* d_out, int out_size)
{
    const float* x    = (const float*)d_in[0];
    const float* Wih1 = (const float*)d_in[1];
    const float* Whh1 = (const float*)d_in[2];
    const float* bih1 = (const float*)d_in[3];
    const float* bhh1 = (const float*)d_in[4];
    const float* Wih2 = (const float*)d_in[5];
    const float* Whh2 = (const float*)d_in[6];
    const float* bih2 = (const float*)d_in[7];
    const float* bhh2 = (const float*)d_in[8];
    const float* Wfc  = (const float*)d_in[9];
    const float* bfc  = (const float*)d_in[10];
    float* out = (float*)d_out;

    const size_t smem_bytes = SMEM_FLOATS * sizeof(float);  // ~213 KB
    cudaFuncSetAttribute(lstm2_fused_kernel,
                         cudaFuncAttributeMaxDynamicSharedMemorySize,
                         (int)smem_bytes);

    lstm2_fused_kernel<<<GRID, BLK, smem_bytes>>>(
        x, Wih1, Whh1, bih1, bhh1, Wih2, Whh2, bih2, bhh2, Wfc, bfc, out);
}

// round 3
// speedup vs baseline: 1.4688x; 1.3107x over previous
#include <cuda_runtime.h>

// Problem constants
#define T_STEPS 168
#define IN_DIM  16
#define NH1     64
#define NH2     32
#define NG1     256   // 4*H1
#define NG2     128   // 4*H2
#define BATCH   4096

// Tiling: one wave — 147 CTAs on 148 SMs, 512 threads each
#define NB   28
#define BLK  512
#define GRID ((BATCH + NB - 1) / NB)   // 147

// Strides (floats): ≡ 0 mod 4 (float4 align), ≡ 4 mod 8 (conflict-free LDS.128)
#define W1_STRIDE  84    // 16 (x) + 64 (h1) + 4 pad
#define W2_STRIDE  100   // 64 (h1) + 32 (h2) + 4 pad
#define IN1_STRIDE 84
#define IN2_STRIDE 100

#define OFF_W1   0
#define OFF_W2   (OFF_W1  + NG1 * W1_STRIDE)    // 21504
#define OFF_B1   (OFF_W2  + NG2 * W2_STRIDE)    // 34304
#define OFF_B2   (OFF_B1  + NG1)                // 34560
#define OFF_WFC  (OFF_B2  + NG2)                // 34688
#define OFF_IN1  (OFF_WFC + 32)                 // 34720
#define OFF_IN2  (OFF_IN1 + NB * IN1_STRIDE)    // 37072
#define OFF_G1   (OFF_IN2 + NB * IN2_STRIDE)    // 39872
#define OFF_G2   (OFF_G1  + NB * NG1)           // 47040
#define OFF_C1   (OFF_G2  + NB * NG2)           // 50624
#define OFF_C2   (OFF_C1  + NB * NH1)           // 52416
#define SMEM_FLOATS (OFF_C2 + NB * NH2)         // 53312 floats = 213248 B

typedef unsigned long long u64;

__device__ __forceinline__ void fma2(u64& d, u64 a, u64 b) {
    asm("fma.rn.f32x2 %0, %1, %2, %0;" : "+l"(d) : "l"(a), "l"(b));
}
__device__ __forceinline__ float pairsum(u64 v) {
    float lo, hi;
    asm("mov.b64 {%0, %1}, %2;" : "=f"(lo), "=f"(hi) : "l"(v));
    return lo + hi;
}

__device__ __forceinline__ float sigm_(float v) {
    v = fminf(fmaxf(v, -30.f), 30.f);
    return __fdividef(1.f, 1.f + __expf(-v));
}
__device__ __forceinline__ float tanh_(float v) {
    v = fminf(fmaxf(v, -15.f), 15.f);
    float e = __expf(2.f * v);
    return __fdividef(e - 1.f, e + 1.f);
}

extern __shared__ float smem[];

__global__ __launch_bounds__(BLK, 1)
void lstm2_fused_kernel(const float* __restrict__ x,
                        const float* __restrict__ Wih1, const float* __restrict__ Whh1,
                        const float* __restrict__ bih1, const float* __restrict__ bhh1,
                        const float* __restrict__ Wih2, const float* __restrict__ Whh2,
                        const float* __restrict__ bih2, const float* __restrict__ bhh2,
                        const float* __restrict__ Wfc,  const float* __restrict__ bfc,
                        float* __restrict__ out)
{
    const int tid = threadIdx.x;
    const int b0  = blockIdx.x * NB;

    float* sW1  = smem + OFF_W1;
    float* sW2  = smem + OFF_W2;
    float* sB1  = smem + OFF_B1;
    float* sB2  = smem + OFF_B2;
    float* sWfc = smem + OFF_WFC;
    float* sIn1 = smem + OFF_IN1;
    float* sIn2 = smem + OFF_IN2;
    float* sG1  = smem + OFF_G1;
    float* sG2  = smem + OFF_G2;
    float* sC1  = smem + OFF_C1;
    float* sC2  = smem + OFF_C2;

    // ---- weights into shared (combined [x;h] rows, padded strides) ----
    for (int i = tid; i < NG1 * W1_STRIDE; i += BLK) {
        int g = i / W1_STRIDE, k = i % W1_STRIDE;
        float v = 0.f;
        if (k < IN_DIM)            v = Wih1[g * IN_DIM + k];
        else if (k < IN_DIM + NH1) v = Whh1[g * NH1 + (k - IN_DIM)];
        sW1[i] = v;
    }
    for (int i = tid; i < NG2 * W2_STRIDE; i += BLK) {
        int g = i / W2_STRIDE, k = i % W2_STRIDE;
        float v = 0.f;
        if (k < NH1)            v = Wih2[g * NH1 + k];
        else if (k < NH1 + NH2) v = Whh2[g * NH2 + (k - NH1)];
        sW2[i] = v;
    }
    if (tid < NG1) sB1[tid] = bih1[tid] + bhh1[tid];
    if (tid < NG2) sB2[tid] = bih2[tid] + bhh2[tid];
    if (tid < NH2) sWfc[tid] = Wfc[tid];
    for (int i = tid; i < NB * IN1_STRIDE; i += BLK) sIn1[i] = 0.f;
    for (int i = tid; i < NB * IN2_STRIDE; i += BLK) sIn2[i] = 0.f;
    for (int i = tid; i < NB * NH1; i += BLK) sC1[i] = 0.f;
    for (int i = tid; i < NB * NH2; i += BLK) sC2[i] = 0.f;

    // ---- x prefetch: 112 threads each own one float4 (b, k4) ----
    const bool xact = (tid < NB * (IN_DIM / 4));          // 112
    const int  xb   = tid >> 2;
    const int  xk4  = tid & 3;
    const bool xval = xact && (b0 + xb) < BATCH;
    const float* xptr = x + ((long)(b0 + xb) * T_STEPS) * IN_DIM + xk4 * 4;
    float4 xreg = make_float4(0.f, 0.f, 0.f, 0.f);
    if (xval) xreg = *(const float4*)xptr;

    __syncthreads();

    // phase 2: 512 threads = 128 gate-pairs (p, p+128) x 4 batch-quarters of 7
    const int p   = tid & 127;
    const int q2  = tid >> 7;           // 0..3
    const float* w1a = sW1 + p * W1_STRIDE;
    const float* w1b = sW1 + (p + 128) * W1_STRIDE;
    const float  bb1a = sB1[p];
    const float  bb1b = sB1[p + 128];
    const bool   b_is_tanh = (p < 64);  // gate p+128 in group 2 iff p<64

    // phase 4: 512 threads = 128 gates x 4 batch-quarters of 7
    const int g2  = tid & 127;
    const int q4  = tid >> 7;
    const float* w2row = sW2 + g2 * W2_STRIDE;
    const float  bb2   = sB2[g2];
    const int    grp2  = g2 >> 5;

    // phase 3: 448 threads = 64 units x 7 batch-groups of 4
    const int u3  = tid & 63;
    const int bq3 = tid >> 6;           // 0..7, group 7 idle
    // phase 5: 448 threads = 32 units x 14 batch-groups of 2
    const int u5  = tid & 31;
    const int bq5 = tid >> 5;           // 0..15, groups 14,15 idle

    for (int t = 0; t < T_STEPS; t++) {
        // ---- phase 1: publish x_t ----
        if (xact) *(float4*)&sIn1[xb * IN1_STRIDE + xk4 * 4] = xreg;
        __syncthreads();                              // A
        if (xval && (t + 1) < T_STEPS)
            xreg = *(const float4*)(xptr + (long)(t + 1) * IN_DIM);

        // ---- phase 2: layer-1 gates (2 gates x 7 batches per thread) ----
        {
            u64 acca[7], accb[7];
#pragma unroll
            for (int b = 0; b < 7; b++) { acca[b] = 0ull; accb[b] = 0ull; }
            const float* in1q = sIn1 + (q2 * 7) * IN1_STRIDE;
#pragma unroll 4
            for (int k4 = 0; k4 < (IN_DIM + NH1) / 4; k4++) {      // 20
                const ulonglong2 wa = *(const ulonglong2*)(w1a + k4 * 4);
                const ulonglong2 wb = *(const ulonglong2*)(w1b + k4 * 4);
#pragma unroll
                for (int b = 0; b < 7; b++) {
                    const ulonglong2 h = *(const ulonglong2*)(in1q + b * IN1_STRIDE + k4 * 4);
                    fma2(acca[b], wa.x, h.x);
                    fma2(acca[b], wa.y, h.y);
                    fma2(accb[b], wb.x, h.x);
                    fma2(accb[b], wb.y, h.y);
                }
            }
#pragma unroll
            for (int b = 0; b < 7; b++) {
                const int bb = q2 * 7 + b;
                const float va = pairsum(acca[b]) + bb1a;
                const float vb = pairsum(accb[b]) + bb1b;
                sG1[bb * NG1 + p]       = sigm_(va);                    // groups 0,1
                sG1[bb * NG1 + 128 + p] = b_is_tanh ? tanh_(vb) : sigm_(vb);
            }
        }
        __syncthreads();                              // B

        // ---- phase 3: layer-1 cell/h update ----
        if (bq3 < 7) {
#pragma unroll
            for (int j = 0; j < 4; j++) {
                const int b = bq3 * 4 + j;
                const float i_ = sG1[b * NG1 + u3];
                const float f_ = sG1[b * NG1 + NH1 + u3];
                const float g_ = sG1[b * NG1 + 2 * NH1 + u3];
                const float o_ = sG1[b * NG1 + 3 * NH1 + u3];
                const float c  = fmaf(f_, sC1[b * NH1 + u3], i_ * g_);
                sC1[b * NH1 + u3] = c;
                const float h = o_ * tanh_(c);
                sIn1[b * IN1_STRIDE + IN_DIM + u3] = h;
                sIn2[b * IN2_STRIDE + u3]          = h;
            }
        }
        __syncthreads();                              // C

        // ---- phase 4: layer-2 gates (1 gate x 7 batches per thread) ----
        {
            u64 acc[7];
#pragma unroll
            for (int b = 0; b < 7; b++) acc[b] = 0ull;
            const float* in2q = sIn2 + (q4 * 7) * IN2_STRIDE;
#pragma unroll 4
            for (int k4 = 0; k4 < (NH1 + NH2) / 4; k4++) {         // 24
                const ulonglong2 w = *(const ulonglong2*)(w2row + k4 * 4);
#pragma unroll
                for (int b = 0; b < 7; b++) {
                    const ulonglong2 h = *(const ulonglong2*)(in2q + b * IN2_STRIDE + k4 * 4);
                    fma2(acc[b], w.x, h.x);
                    fma2(acc[b], w.y, h.y);
                }
            }
#pragma unroll
            for (int b = 0; b < 7; b++) {
                const float v = pairsum(acc[b]) + bb2;
                sG2[(q4 * 7 + b) * NG2 + g2] = (grp2 == 2) ? tanh_(v) : sigm_(v);
            }
        }
        __syncthreads();                              // D

        // ---- phase 5: layer-2 cell/h update ----
        if (bq5 < 14) {
#pragma unroll
            for (int j = 0; j < 2; j++) {
                const int b = bq5 * 2 + j;
                const float i_ = sG2[b * NG2 + u5];
                const float f_ = sG2[b * NG2 + NH2 + u5];
                const float g_ = sG2[b * NG2 + 2 * NH2 + u5];
                const float o_ = sG2[b * NG2 + 3 * NH2 + u5];
                const float c  = fmaf(f_, sC2[b * NH2 + u5], i_ * g_);
                sC2[b * NH2 + u5] = c;
                sIn2[b * IN2_STRIDE + NH1 + u5] = o_ * tanh_(c);
            }
        }
        // no sync needed: next readers of sIn2/sC2 are behind barriers A,B,C of t+1
    }

    __syncthreads();

    // ---- final FC: out[b] = h2_last . Wfc + bfc ----
    if (tid < NB) {
        const int bg = b0 + tid;
        if (bg < BATCH) {
            float s = bfc[0];
#pragma unroll
            for (int u = 0; u < NH2; u++)
                s = fmaf(sIn2[tid * IN2_STRIDE + NH1 + u], sWfc[u], s);
            out[bg] = s;
        }
    }
}

extern "C" void kernel_launch(void* const* d_in, const int* in_sizes, int n_in,
                              void* d_out, int out_size)
{
    const float* x    = (const float*)d_in[0];
    const float* Wih1 = (const float*)d_in[1];
    const float* Whh1 = (const float*)d_in[2];
    const float* bih1 = (const float*)d_in[3];
    const float* bhh1 = (const float*)d_in[4];
    const float* Wih2 = (const float*)d_in[5];
    const float* Whh2 = (const float*)d_in[6];
    const float* bih2 = (const float*)d_in[7];
    const float* bhh2 = (const float*)d_in[8];
    const float* Wfc  = (const float*)d_in[9];
    const float* bfc  = (const float*)d_in[10];
    float* out = (float*)d_out;

    const size_t smem_bytes = SMEM_FLOATS * sizeof(float);  // ~213 KB
    cudaFuncSetAttribute(lstm2_fused_kernel,
                         cudaFuncAttributeMaxDynamicSharedMemorySize,
                         (int)smem_bytes);

    lstm2_fused_kernel<<<GRID, BLK, smem_bytes>>>(
        x, Wih1, Whh1, bih1, bhh1, Wih2, Whh2, bih2, bhh2, Wfc, bfc, out);
}